// round 4
// baseline (speedup 1.0000x reference)
#include <cuda_runtime.h>
#include <cuda_bf16.h>
#include <cstdint>

#define C_DIM 512
#define K_DIM 150
#define K_PAD 160
#define N_MAX 262144

// ---------------- device scratch (zero-initialized; rows 150..159 never written) ----
__device__ __nv_bfloat16 g_probs_hi[(size_t)K_PAD * N_MAX];
__device__ __nv_bfloat16 g_probs_lo[(size_t)K_PAD * N_MAX];
__device__ float g_acc[C_DIM * K_PAD];   // acc[c][k]
__device__ float g_S[K_PAD];

// ---------------- PTX helpers (arch-agnostic sm_80-level only) ----------------
__device__ __forceinline__ uint32_t smem_u32(const void* p) {
    uint32_t a;
    asm("{ .reg .u64 t; cvta.to.shared.u64 t, %1; cvt.u32.u64 %0, t; }" : "=r"(a) : "l"(p));
    return a;
}
__device__ __forceinline__ void cp16(uint32_t dst, const void* src) {
    asm volatile("cp.async.ca.shared.global [%0], [%1], 16;" :: "r"(dst), "l"(src) : "memory");
}
#define CP_COMMIT() asm volatile("cp.async.commit_group;" ::: "memory")
#define CP_WAIT1()  asm volatile("cp.async.wait_group 1;" ::: "memory")

#define LDSM_X4(r0, r1, r2, r3, addr) \
    asm volatile("ldmatrix.sync.aligned.m8n8.x4.shared.b16 {%0,%1,%2,%3}, [%4];" \
        : "=r"(r0), "=r"(r1), "=r"(r2), "=r"(r3) : "r"(addr))

#define MMA_BF16(d, a0, a1, a2, a3, b0, b1) \
    asm volatile("mma.sync.aligned.m16n8k16.row.col.f32.bf16.bf16.f32 " \
        "{%0,%1,%2,%3}, {%4,%5,%6,%7}, {%8,%9}, {%0,%1,%2,%3};" \
        : "+f"((d)[0]), "+f"((d)[1]), "+f"((d)[2]), "+f"((d)[3]) \
        : "r"(a0), "r"(a1), "r"(a2), "r"(a3), "r"(b0), "r"(b1))

// f32 pair -> packed bf16x2 hi + lo(residual)
__device__ __forceinline__ void cvt_hl(float2 v, uint32_t& h, uint32_t& l) {
    __nv_bfloat162 hb = __float22bfloat162_rn(v);
    __nv_bfloat162 lb = __float22bfloat162_rn(
        make_float2(v.x - __bfloat162float(hb.x), v.y - __bfloat162float(hb.y)));
    h = *reinterpret_cast<uint32_t*>(&hb);
    l = *reinterpret_cast<uint32_t*>(&lb);
}

// ---------------- K0: zero accumulators ----------------
__global__ void zero_kernel() {
    int i = blockIdx.x * blockDim.x + threadIdx.x;
    if (i < C_DIM * K_PAD) g_acc[i] = 0.0f;
    if (i < K_PAD) g_S[i] = 0.0f;
}

// ---------------- K1: online softmax -> bf16 hi/lo probs + column sums ----------------
__global__ __launch_bounds__(256) void softmax_kernel(const float* __restrict__ logits, int N) {
    __shared__ float Ssh[K_DIM];
    int tid = threadIdx.x;
    if (tid < K_DIM) Ssh[tid] = 0.0f;
    __syncthreads();

    size_t n = (size_t)blockIdx.x * 256 + tid;

    float m = -3.0e38f, z = 0.0f;
    #pragma unroll 5
    for (int k = 0; k < K_DIM; k++) {
        float l = logits[(size_t)k * N + n];
        float m2 = fmaxf(m, l);
        z = z * __expf(m - m2) + __expf(l - m2);
        m = m2;
    }
    float invz = 1.0f / z;

    #pragma unroll 5
    for (int k = 0; k < K_DIM; k++) {
        float l = logits[(size_t)k * N + n];
        float p = __expf(l - m) * invz;
        __nv_bfloat16 h = __float2bfloat16(p);
        g_probs_hi[(size_t)k * N + n] = h;
        g_probs_lo[(size_t)k * N + n] = __float2bfloat16(p - __bfloat162float(h));
        float w = p;
        #pragma unroll
        for (int o = 16; o; o >>= 1) w += __shfl_xor_sync(0xffffffffu, w, o);
        if ((tid & 31) == 0) atomicAdd(&Ssh[k], w);
    }
    __syncthreads();
    if (tid < K_DIM) atomicAdd(&g_S[tid], Ssh[tid]);
}

// ---------------- K2: HMMA GEMM  acc[c][k] += sum_n f[c,n] * p[k,n] ----------------
// Split precision: f = fh + fl, p = ph + pl;  D += fh*ph + fh*pl + fl*ph
// CTA: M=128 x N=160, 8 warps = 8(M) x 1(N); warp tile 16 x 160.
// A: gmem f32 -> regs -> bf16 hi/lo frags (no smem). B: 3-stage cp.async ring.
#define KC       32
#define SPLITS   74
#define BH_OFF   0        // 160 rows x 80B (64B data + 16 pad)
#define BL_OFF   12800
#define STAGE_B  25600
#define GEMM_SMEM (3 * STAGE_B)   // 76800

__device__ __forceinline__ void issue_B(uint32_t sb, size_t n0, int tid, int N) {
    #pragma unroll
    for (int i = 0; i < 5; i++) {
        int idx = tid + i * 256;            // 0..1279
        int arr = idx >= 640;
        int j = arr ? idx - 640 : idx;
        int r = j >> 2, u = j & 3;
        const __nv_bfloat16* base = arr ? g_probs_lo : g_probs_hi;
        cp16(sb + (arr ? BL_OFF : BH_OFF) + r * 80 + u * 16,
             (const char*)(base + (size_t)r * N + n0) + u * 16);
    }
}

__global__ __launch_bounds__(256, 2) void gemm_kernel(const float* __restrict__ feats, int N) {
    extern __shared__ char smem[];
    uint32_t sb0 = smem_u32(smem);
    int tid = threadIdx.x, lane = tid & 31, w = tid >> 5;
    int c0 = blockIdx.y * 128;
    int split = blockIdx.x;
    int cnt = (N / KC - 1 - split) / SPLITS + 1;

    float acc[20][4];
    #pragma unroll
    for (int nf = 0; nf < 20; nf++)
        #pragma unroll
        for (int q = 0; q < 4; q++) acc[nf][q] = 0.0f;

    // A addressing: warp owns rows [c0+w*16, +16)
    const float* A0 = feats + (size_t)(c0 + w * 16 + (lane >> 2)) * N + (lane & 3) * 2;
    const float* A1 = A0 + (size_t)8 * N;

    float2 fb[8];
    // prologue: A chunk 0 -> regs, B chunks 0,1 -> stages 0,1
    {
        size_t n = (size_t)split * KC;
        fb[0] = *(const float2*)(A0 + n);      fb[1] = *(const float2*)(A1 + n);
        fb[2] = *(const float2*)(A0 + n + 8);  fb[3] = *(const float2*)(A1 + n + 8);
        fb[4] = *(const float2*)(A0 + n + 16); fb[5] = *(const float2*)(A1 + n + 16);
        fb[6] = *(const float2*)(A0 + n + 24); fb[7] = *(const float2*)(A1 + n + 24);
        issue_B(sb0, n, tid, N);
        CP_COMMIT();
        if (cnt > 1) issue_B(sb0 + STAGE_B, n + (size_t)SPLITS * KC, tid, N);
        CP_COMMIT();
    }

    uint32_t b_base = (uint32_t)(((lane & 7) + ((lane >> 4) & 1) * 8) * 80 + ((lane >> 3) & 1) * 16);

    for (int j = 0; j < cnt; j++) {
        uint32_t sb = sb0 + (uint32_t)(j % 3) * STAGE_B;
        CP_WAIT1();                  // B stage for chunk j complete
        __syncthreads();             // all warps done with chunk j-1's stage

        // convert A chunk j: fb -> bf16 hi/lo fragments (fb becomes free)
        uint32_t Ah[2][4], Al[2][4];
        #pragma unroll
        for (int k16 = 0; k16 < 2; k16++)
            #pragma unroll
            for (int q = 0; q < 4; q++)
                cvt_hl(fb[k16 * 4 + q], Ah[k16][q], Al[k16][q]);

        // prefetch A chunk j+1
        if (j + 1 < cnt) {
            size_t n = ((size_t)split + (size_t)(j + 1) * SPLITS) * KC;
            fb[0] = *(const float2*)(A0 + n);      fb[1] = *(const float2*)(A1 + n);
            fb[2] = *(const float2*)(A0 + n + 8);  fb[3] = *(const float2*)(A1 + n + 8);
            fb[4] = *(const float2*)(A0 + n + 16); fb[5] = *(const float2*)(A1 + n + 16);
            fb[6] = *(const float2*)(A0 + n + 24); fb[7] = *(const float2*)(A1 + n + 24);
        }
        // issue B chunk j+2
        if (j + 2 < cnt)
            issue_B(sb0 + (uint32_t)((j + 2) % 3) * STAGE_B,
                    ((size_t)split + (size_t)(j + 2) * SPLITS) * KC, tid, N);
        CP_COMMIT();                 // commit (possibly empty) keeps group accounting

        // compute chunk j
        #pragma unroll
        for (int k16 = 0; k16 < 2; k16++) {
            uint32_t ko = (uint32_t)k16 * 32;
            #pragma unroll
            for (int nfp = 0; nfp < 10; nfp++) {
                uint32_t bh0, bh1, bh2, bh3, bl0, bl1, bl2, bl3;
                uint32_t ba = sb + b_base + (uint32_t)nfp * 1280 + ko;
                LDSM_X4(bh0, bh1, bh2, bh3, ba + BH_OFF);
                LDSM_X4(bl0, bl1, bl2, bl3, ba + BL_OFF);
                MMA_BF16(acc[2*nfp],   Ah[k16][0], Ah[k16][1], Ah[k16][2], Ah[k16][3], bh0, bh1);
                MMA_BF16(acc[2*nfp],   Ah[k16][0], Ah[k16][1], Ah[k16][2], Ah[k16][3], bl0, bl1);
                MMA_BF16(acc[2*nfp],   Al[k16][0], Al[k16][1], Al[k16][2], Al[k16][3], bh0, bh1);
                MMA_BF16(acc[2*nfp+1], Ah[k16][0], Ah[k16][1], Ah[k16][2], Ah[k16][3], bh2, bh3);
                MMA_BF16(acc[2*nfp+1], Ah[k16][0], Ah[k16][1], Ah[k16][2], Ah[k16][3], bl2, bl3);
                MMA_BF16(acc[2*nfp+1], Al[k16][0], Al[k16][1], Al[k16][2], Al[k16][3], bh2, bh3);
            }
        }
    }

    // epilogue: reduce partials into g_acc
    int g = lane >> 2, tg = lane & 3;
    int row = c0 + w * 16 + g;
    #pragma unroll
    for (int nf = 0; nf < 20; nf++) {
        int col = nf * 8 + tg * 2;
        atomicAdd(&g_acc[row * K_PAD + col],           acc[nf][0]);
        atomicAdd(&g_acc[row * K_PAD + col + 1],       acc[nf][1]);
        atomicAdd(&g_acc[(row + 8) * K_PAD + col],     acc[nf][2]);
        atomicAdd(&g_acc[(row + 8) * K_PAD + col + 1], acc[nf][3]);
    }
}

// ---------------- K3: finalize  out[k][c] = acc[c][k] / max(S[k], 1e-6) ----------------
__global__ void finalize_kernel(float* __restrict__ out) {
    int k = blockIdx.x, ci = threadIdx.x;
    out[k * C_DIM + ci] = g_acc[ci * K_PAD + k] / fmaxf(g_S[k], 1e-6f);
}

// ---------------- launch ----------------
extern "C" void kernel_launch(void* const* d_in, const int* in_sizes, int n_in,
                              void* d_out, int out_size) {
    const float* feats  = (const float*)d_in[0];   // (512, H, W)
    const float* logits = (const float*)d_in[1];   // (150, H, W)
    float* out = (float*)d_out;                    // (150, 512)
    int N = in_sizes[0] / C_DIM;                   // 262144

    cudaFuncSetAttribute(gemm_kernel, cudaFuncAttributeMaxDynamicSharedMemorySize, GEMM_SMEM);

    zero_kernel<<<(C_DIM * K_PAD + 255) / 256, 256>>>();
    softmax_kernel<<<N / 256, 256>>>(logits, N);
    gemm_kernel<<<dim3(SPLITS, C_DIM / 128), 256, GEMM_SMEM>>>(feats, N);
    finalize_kernel<<<K_DIM, C_DIM>>>(out);
}

// round 5
// speedup vs baseline: 1.0694x; 1.0694x over previous
#include <cuda_runtime.h>
#include <cuda_bf16.h>
#include <cstdint>

#define C_DIM 512
#define K_DIM 150
#define K_PAD 160
#define KC    32
#define SPLITS 37

// ---------------- device scratch ----------------
__device__ float g_acc[C_DIM * K_PAD];   // acc[c][k]
__device__ float g_S[K_PAD];

// ---------------- PTX helpers (arch-agnostic sm_80-level only) ----------------
__device__ __forceinline__ uint32_t smem_u32(const void* p) {
    uint32_t a;
    asm("{ .reg .u64 t; cvta.to.shared.u64 t, %1; cvt.u32.u64 %0, t; }" : "=r"(a) : "l"(p));
    return a;
}
__device__ __forceinline__ void cp16(uint32_t dst, const void* src) {
    asm volatile("cp.async.ca.shared.global [%0], [%1], 16;" :: "r"(dst), "l"(src) : "memory");
}
#define CP_COMMIT() asm volatile("cp.async.commit_group;" ::: "memory")
#define CP_WAIT1()  asm volatile("cp.async.wait_group 1;" ::: "memory")

#define LDSM_X4(r0, r1, r2, r3, addr) \
    asm volatile("ldmatrix.sync.aligned.m8n8.x4.shared.b16 {%0,%1,%2,%3}, [%4];" \
        : "=r"(r0), "=r"(r1), "=r"(r2), "=r"(r3) : "r"(addr))

#define MMA_BF16(d, a0, a1, a2, a3, b0, b1) \
    asm volatile("mma.sync.aligned.m16n8k16.row.col.f32.bf16.bf16.f32 " \
        "{%0,%1,%2,%3}, {%4,%5,%6,%7}, {%8,%9}, {%0,%1,%2,%3};" \
        : "+f"((d)[0]), "+f"((d)[1]), "+f"((d)[2]), "+f"((d)[3]) \
        : "r"(a0), "r"(a1), "r"(a2), "r"(a3), "r"(b0), "r"(b1))

__device__ __forceinline__ void cvt_hl(float2 v, uint32_t& h, uint32_t& l) {
    __nv_bfloat162 hb = __float22bfloat162_rn(v);
    __nv_bfloat162 lb = __float22bfloat162_rn(
        make_float2(v.x - __bfloat162float(hb.x), v.y - __bfloat162float(hb.y)));
    h = *reinterpret_cast<uint32_t*>(&hb);
    l = *reinterpret_cast<uint32_t*>(&lb);
}

// ---------------- smem layout ----------------
// 3 logits stages: 150 rows x 144B (32 f32 + pad)      -> 21632 B each
// 2 B-tile buffers: hi 160x80B + lo 160x80B = 25600 B  -> 51200 B
#define L_STRIDE 144
#define L_STAGE  21632
#define B_BASE   (3 * L_STAGE)          // 64896
#define B_PAIR   25600
#define BL_OFF   12800
#define SMEM_TOT (B_BASE + 2 * B_PAIR)  // 116096

// ---------------- K0: zero accumulators ----------------
__global__ void zero_kernel() {
    int i = blockIdx.x * blockDim.x + threadIdx.x;
    if (i < C_DIM * K_PAD) g_acc[i] = 0.0f;
    if (i < K_PAD) g_S[i] = 0.0f;
}

__device__ __forceinline__ void issue_logits(uint32_t sb0, int s, const float* __restrict__ logits,
                                             size_t n0, int tid, int N) {
    #pragma unroll
    for (int i = 0; i < 5; i++) {
        int idx = tid + i * 256;                  // 150 rows x 8 units = 1200
        if (idx < 1200) {
            int r = idx >> 3, u = idx & 7;
            cp16(sb0 + (uint32_t)s * L_STAGE + r * L_STRIDE + u * 16,
                 (const void*)(logits + (size_t)r * N + n0 + u * 4));
        }
    }
}

// ---------------- fused kernel: softmax-in-GEMM ----------------
// acc[c][k] += sum_n f[c,n] * softmax_k(logits[.,n]);  split f/p into bf16 hi+lo, 3 MMAs.
// CTA: M=128 (C rows) x N=160 (classes). 8 warps along M. A in registers, B built in smem.
__global__ __launch_bounds__(256, 1) void fused_kernel(const float* __restrict__ feats,
                                                       const float* __restrict__ logits, int N) {
    extern __shared__ char smem[];
    uint32_t sb0 = smem_u32(smem);
    int tid = threadIdx.x, lane = tid & 31, w = tid >> 5;
    int c0 = blockIdx.y * 128;
    int split = blockIdx.x;
    int cnt = (N / KC - 1 - split) / SPLITS + 1;

    // zero the B pad rows (k=150..159) of both buffers, both arrays (never written again)
    for (int i = tid; i < 800; i += 256) {
        int reg = i / 200, off = i % 200;
        *(uint32_t*)(smem + B_BASE + (reg >> 1) * B_PAIR + (reg & 1) * BL_OFF + 150 * 80 + off * 4) = 0u;
    }

    float acc[20][4];
    #pragma unroll
    for (int nf = 0; nf < 20; nf++)
        #pragma unroll
        for (int q = 0; q < 4; q++) acc[nf][q] = 0.0f;

    float S_part[19];
    #pragma unroll
    for (int i = 0; i < 19; i++) S_part[i] = 0.0f;

    // A addressing: warp owns feats rows [c0+w*16, +16)
    const float* A0 = feats + (size_t)(c0 + w * 16 + (lane >> 2)) * N + (lane & 3) * 2;
    const float* A1 = A0 + (size_t)8 * N;

    // softmax role: 8 threads per pixel column
    int g = tid >> 3, t8 = tid & 7;

    float2 fb[8];
    {   // prologue
        size_t n = (size_t)split * KC;
        fb[0] = *(const float2*)(A0 + n);      fb[1] = *(const float2*)(A1 + n);
        fb[2] = *(const float2*)(A0 + n + 8);  fb[3] = *(const float2*)(A1 + n + 8);
        fb[4] = *(const float2*)(A0 + n + 16); fb[5] = *(const float2*)(A1 + n + 16);
        fb[6] = *(const float2*)(A0 + n + 24); fb[7] = *(const float2*)(A1 + n + 24);
        issue_logits(sb0, 0, logits, n, tid, N);
        CP_COMMIT();
        if (cnt > 1) issue_logits(sb0, 1, logits, n + (size_t)SPLITS * KC, tid, N);
        CP_COMMIT();
    }

    uint32_t b_base = (uint32_t)(((lane & 7) + ((lane >> 4) & 1) * 8) * 80 + ((lane >> 3) & 1) * 16);

    for (int j = 0; j < cnt; j++) {
        CP_WAIT1();                   // logits stage j complete
        __syncthreads();              // visible to CTA; prior-iter users of B(j%2) done

        // convert A chunk j to fragments (frees fb)
        uint32_t Ah[2][4], Al[2][4];
        #pragma unroll
        for (int k16 = 0; k16 < 2; k16++)
            #pragma unroll
            for (int q = 0; q < 4; q++)
                cvt_hl(fb[k16 * 4 + q], Ah[k16][q], Al[k16][q]);

        // ---- softmax for this chunk: logits stage (j%3) -> B buffer (j%2) ----
        {
            const char* Ls = smem + (j % 3) * L_STAGE;
            float vals[19];
            float m = -3.0e38f;
            #pragma unroll
            for (int i = 0; i < 19; i++) {
                int k = t8 + 8 * i;
                vals[i] = (k < K_DIM) ? *(const float*)(Ls + k * L_STRIDE + g * 4) : -3.0e38f;
                m = fmaxf(m, vals[i]);
            }
            m = fmaxf(m, __shfl_xor_sync(0xffffffffu, m, 1));
            m = fmaxf(m, __shfl_xor_sync(0xffffffffu, m, 2));
            m = fmaxf(m, __shfl_xor_sync(0xffffffffu, m, 4));
            float z = 0.0f;
            #pragma unroll
            for (int i = 0; i < 19; i++) { vals[i] = __expf(vals[i] - m); z += vals[i]; }
            z += __shfl_xor_sync(0xffffffffu, z, 1);
            z += __shfl_xor_sync(0xffffffffu, z, 2);
            z += __shfl_xor_sync(0xffffffffu, z, 4);
            float invz = 1.0f / z;
            char* bh = smem + B_BASE + (j % 2) * B_PAIR;
            char* bl = bh + BL_OFF;
            #pragma unroll
            for (int i = 0; i < 19; i++) {
                int k = t8 + 8 * i;
                if (k < K_DIM) {
                    float p = vals[i] * invz;
                    S_part[i] += p;
                    __nv_bfloat16 h = __float2bfloat16(p);
                    __nv_bfloat16 l = __float2bfloat16(p - __bfloat162float(h));
                    *(uint16_t*)(bh + k * 80 + g * 2) = *(uint16_t*)&h;
                    *(uint16_t*)(bl + k * 80 + g * 2) = *(uint16_t*)&l;
                }
            }
        }

        // issue logits chunk j+2; prefetch A chunk j+1
        if (j + 2 < cnt)
            issue_logits(sb0, (j + 2) % 3, logits,
                         ((size_t)split + (size_t)(j + 2) * SPLITS) * KC, tid, N);
        CP_COMMIT();
        if (j + 1 < cnt) {
            size_t n = ((size_t)split + (size_t)(j + 1) * SPLITS) * KC;
            fb[0] = *(const float2*)(A0 + n);      fb[1] = *(const float2*)(A1 + n);
            fb[2] = *(const float2*)(A0 + n + 8);  fb[3] = *(const float2*)(A1 + n + 8);
            fb[4] = *(const float2*)(A0 + n + 16); fb[5] = *(const float2*)(A1 + n + 16);
            fb[6] = *(const float2*)(A0 + n + 24); fb[7] = *(const float2*)(A1 + n + 24);
        }
        __syncthreads();              // B tiles visible

        // ---- compute chunk j ----
        uint32_t sb = sb0 + B_BASE + (uint32_t)(j % 2) * B_PAIR;
        #pragma unroll
        for (int k16 = 0; k16 < 2; k16++) {
            uint32_t ko = (uint32_t)k16 * 32;
            #pragma unroll
            for (int nfp = 0; nfp < 10; nfp++) {
                uint32_t bh0, bh1, bh2, bh3, bl0, bl1, bl2, bl3;
                uint32_t ba = sb + b_base + (uint32_t)nfp * 1280 + ko;
                LDSM_X4(bh0, bh1, bh2, bh3, ba);
                LDSM_X4(bl0, bl1, bl2, bl3, ba + BL_OFF);
                MMA_BF16(acc[2*nfp],   Ah[k16][0], Ah[k16][1], Ah[k16][2], Ah[k16][3], bh0, bh1);
                MMA_BF16(acc[2*nfp],   Ah[k16][0], Ah[k16][1], Ah[k16][2], Ah[k16][3], bl0, bl1);
                MMA_BF16(acc[2*nfp],   Al[k16][0], Al[k16][1], Al[k16][2], Al[k16][3], bh0, bh1);
                MMA_BF16(acc[2*nfp+1], Ah[k16][0], Ah[k16][1], Ah[k16][2], Ah[k16][3], bh2, bh3);
                MMA_BF16(acc[2*nfp+1], Ah[k16][0], Ah[k16][1], Ah[k16][2], Ah[k16][3], bl2, bl3);
                MMA_BF16(acc[2*nfp+1], Al[k16][0], Al[k16][1], Al[k16][2], Al[k16][3], bh2, bh3);
            }
        }
    }

    // ---- epilogue ----
    int gr = lane >> 2, tg = lane & 3;
    int row = c0 + w * 16 + gr;
    #pragma unroll
    for (int nf = 0; nf < 20; nf++) {
        int col = nf * 8 + tg * 2;
        atomicAdd(&g_acc[row * K_PAD + col],           acc[nf][0]);
        atomicAdd(&g_acc[row * K_PAD + col + 1],       acc[nf][1]);
        atomicAdd(&g_acc[(row + 8) * K_PAD + col],     acc[nf][2]);
        atomicAdd(&g_acc[(row + 8) * K_PAD + col + 1], acc[nf][3]);
    }
    if (blockIdx.y == 0) {
        #pragma unroll
        for (int i = 0; i < 19; i++) {
            int k = t8 + 8 * i;
            if (k < K_DIM) atomicAdd(&g_S[k], S_part[i]);
        }
    }
}

// ---------------- finalize ----------------
__global__ void finalize_kernel(float* __restrict__ out) {
    int k = blockIdx.x, ci = threadIdx.x;
    out[k * C_DIM + ci] = g_acc[ci * K_PAD + k] / fmaxf(g_S[k], 1e-6f);
}

// ---------------- launch ----------------
extern "C" void kernel_launch(void* const* d_in, const int* in_sizes, int n_in,
                              void* d_out, int out_size) {
    const float* feats  = (const float*)d_in[0];   // (512, H, W)
    const float* logits = (const float*)d_in[1];   // (150, H, W)
    float* out = (float*)d_out;                    // (150, 512)
    int N = in_sizes[0] / C_DIM;                   // 262144

    cudaFuncSetAttribute(fused_kernel, cudaFuncAttributeMaxDynamicSharedMemorySize, SMEM_TOT);

    zero_kernel<<<(C_DIM * K_PAD + 255) / 256, 256>>>();
    fused_kernel<<<dim3(SPLITS, C_DIM / 128), 256, SMEM_TOT>>>(feats, logits, N);
    finalize_kernel<<<K_DIM, C_DIM>>>(out);
}